// round 10
// baseline (speedup 1.0000x reference)
#include <cuda_runtime.h>
#include <mma.h>
#include <math.h>

using namespace nvcuda;

#define B_ 8
#define S_ 2048
#define D_ 768

constexpr int BM = 128, BN = 128, BK = 16, KP = BK + 4;
constexpr int BNP = BN + 4;  // stride for [k][n] B-tile layout (NN path)

// Scratch (allocation-free contract: __device__ globals)
__device__ float g_Q[(size_t)B_ * S_ * D_];
__device__ float g_K[(size_t)B_ * S_ * D_];
__device__ float g_V[(size_t)B_ * S_ * D_];
__device__ float g_P[(size_t)B_ * S_ * S_];
__device__ float g_O[(size_t)B_ * S_ * D_];

// ---- cp.async helpers (16B) ----
__device__ __forceinline__ void cp_async16(void* smem_dst, const void* gmem_src) {
    unsigned dst = (unsigned)__cvta_generic_to_shared(smem_dst);
    asm volatile("cp.async.cg.shared.global [%0], [%1], 16;\n" :: "r"(dst), "l"(gmem_src));
}
__device__ __forceinline__ void cp_async_commit() {
    asm volatile("cp.async.commit_group;\n");
}
template <int N>
__device__ __forceinline__ void cp_async_wait() {
    asm volatile("cp.async.wait_group %0;\n" :: "n"(N));
}

// C[m,n] = alpha * sum_k A[m,k] * Bx[n,k]
// BLAYOUT 0: Bm is [N,K] row-major (ldb = K stride) -> "NT" gemm (x @ W^T). Smem Bs = [n][k].
// BLAYOUT 1: Bm is [K,N] row-major (ldb = N stride) -> "NN" gemm (P @ V).   Smem Bs = [k][n].
template <int BLAYOUT>
__global__ __launch_bounds__(256) void gemm_kernel(
    const float* __restrict__ A, const float* __restrict__ Bm, float* __restrict__ C,
    int K, int lda, int ldb, int ldc, float alpha,
    long long strideA, long long strideB, long long strideC)
{
    __shared__ float As[2][BM * KP];
    __shared__ float Bs[2][BN * KP];   // holds [n][k] (layout0, 128*20) or [k][n] (layout1, 16*132)

    const int tid = threadIdx.x;
    const int m0 = blockIdx.y * BM;
    const int n0 = blockIdx.x * BN;
    A  += (long long)blockIdx.z * strideA;
    Bm += (long long)blockIdx.z * strideB;
    C  += (long long)blockIdx.z * strideC;

    const int warpId = tid >> 5;
    const int wm0 = (warpId >> 2) * 64;  // 2 warp-rows
    const int wn0 = (warpId & 3) * 32;   // 4 warp-cols

    // per-thread load coordinates (fixed across iterations)
    const int a_row = tid >> 2;          // 0..63  (plus +64 for second half)
    const int a_kq  = tid & 3;           // float4 index in k
    const int b1_k  = tid >> 5;          // 0..7   (plus +8 for second half)   [layout1]
    const int b1_nq = tid & 31;          // float4 index in n                  [layout1]

    // ---- tile load issue (stage s into buffer b) ----
    auto issue_tile = [&](int k0, int b) {
        // A tile: BM x BK = 512 float4, 2 per thread
        cp_async16(&As[b][a_row * KP + a_kq * 4],
                   &A[(size_t)(m0 + a_row) * lda + k0 + a_kq * 4]);
        cp_async16(&As[b][(a_row + 64) * KP + a_kq * 4],
                   &A[(size_t)(m0 + a_row + 64) * lda + k0 + a_kq * 4]);
        if (BLAYOUT == 0) {
            cp_async16(&Bs[b][a_row * KP + a_kq * 4],
                       &Bm[(size_t)(n0 + a_row) * ldb + k0 + a_kq * 4]);
            cp_async16(&Bs[b][(a_row + 64) * KP + a_kq * 4],
                       &Bm[(size_t)(n0 + a_row + 64) * ldb + k0 + a_kq * 4]);
        } else {
            cp_async16(&Bs[b][b1_k * BNP + b1_nq * 4],
                       &Bm[(size_t)(k0 + b1_k) * ldb + n0 + b1_nq * 4]);
            cp_async16(&Bs[b][(b1_k + 8) * BNP + b1_nq * 4],
                       &Bm[(size_t)(k0 + b1_k + 8) * ldb + n0 + b1_nq * 4]);
        }
        cp_async_commit();
    };

    wmma::fragment<wmma::accumulator, 16, 16, 8, float> acc[4][2];
    #pragma unroll
    for (int i = 0; i < 4; i++)
        #pragma unroll
        for (int j = 0; j < 2; j++)
            wmma::fill_fragment(acc[i][j], 0.0f);

    const int nIter = K / BK;
    issue_tile(0, 0);

    for (int it = 0; it < nIter; it++) {
        if (it + 1 < nIter) {
            issue_tile((it + 1) * BK, (it + 1) & 1);
            cp_async_wait<1>();
        } else {
            cp_async_wait<0>();
        }
        __syncthreads();

        const int b = it & 1;
        #pragma unroll
        for (int kk = 0; kk < BK; kk += 8) {
            wmma::fragment<wmma::matrix_a, 16, 16, 8, wmma::precision::tf32, wmma::row_major> af[4];
            #pragma unroll
            for (int i = 0; i < 4; i++) {
                wmma::load_matrix_sync(af[i], &As[b][(wm0 + i * 16) * KP + kk], KP);
                #pragma unroll
                for (int t = 0; t < af[i].num_elements; t++)
                    af[i].x[t] = wmma::__float_to_tf32(af[i].x[t]);
            }
            if (BLAYOUT == 0) {
                wmma::fragment<wmma::matrix_b, 16, 16, 8, wmma::precision::tf32, wmma::col_major> bf[2];
                #pragma unroll
                for (int j = 0; j < 2; j++) {
                    wmma::load_matrix_sync(bf[j], &Bs[b][(wn0 + j * 16) * KP + kk], KP);
                    #pragma unroll
                    for (int t = 0; t < bf[j].num_elements; t++)
                        bf[j].x[t] = wmma::__float_to_tf32(bf[j].x[t]);
                }
                #pragma unroll
                for (int i = 0; i < 4; i++)
                    #pragma unroll
                    for (int j = 0; j < 2; j++)
                        wmma::mma_sync(acc[i][j], af[i], bf[j], acc[i][j]);
            } else {
                wmma::fragment<wmma::matrix_b, 16, 16, 8, wmma::precision::tf32, wmma::row_major> bf[2];
                #pragma unroll
                for (int j = 0; j < 2; j++) {
                    wmma::load_matrix_sync(bf[j], &Bs[b][kk * BNP + wn0 + j * 16], BNP);
                    #pragma unroll
                    for (int t = 0; t < bf[j].num_elements; t++)
                        bf[j].x[t] = wmma::__float_to_tf32(bf[j].x[t]);
                }
                #pragma unroll
                for (int i = 0; i < 4; i++)
                    #pragma unroll
                    for (int j = 0; j < 2; j++)
                        wmma::mma_sync(acc[i][j], af[i], bf[j], acc[i][j]);
            }
        }
        __syncthreads();  // all warps done with buffer b before it is refilled
    }

    #pragma unroll
    for (int i = 0; i < 4; i++)
        #pragma unroll
        for (int j = 0; j < 2; j++) {
            #pragma unroll
            for (int t = 0; t < acc[i][j].num_elements; t++)
                acc[i][j].x[t] *= alpha;
            wmma::store_matrix_sync(
                &C[(size_t)(m0 + wm0 + i * 16) * ldc + n0 + wn0 + j * 16],
                acc[i][j], ldc, wmma::mem_row_major);
        }
}

// Row softmax over g_P rows of length S_ (one block per row, 256 threads, 8 elems each)
__global__ __launch_bounds__(256) void softmax_kernel(float* __restrict__ P)
{
    float4* row = reinterpret_cast<float4*>(P + (size_t)blockIdx.x * S_);
    const int tid = threadIdx.x;
    float4 v0 = row[tid];
    float4 v1 = row[tid + 256];

    float mx = fmaxf(fmaxf(fmaxf(v0.x, v0.y), fmaxf(v0.z, v0.w)),
                     fmaxf(fmaxf(v1.x, v1.y), fmaxf(v1.z, v1.w)));
    __shared__ float red[8];
    #pragma unroll
    for (int o = 16; o > 0; o >>= 1) mx = fmaxf(mx, __shfl_xor_sync(0xffffffffu, mx, o));
    if ((tid & 31) == 0) red[tid >> 5] = mx;
    __syncthreads();
    mx = red[0];
    #pragma unroll
    for (int i = 1; i < 8; i++) mx = fmaxf(mx, red[i]);
    __syncthreads();

    v0.x = __expf(v0.x - mx); v0.y = __expf(v0.y - mx);
    v0.z = __expf(v0.z - mx); v0.w = __expf(v0.w - mx);
    v1.x = __expf(v1.x - mx); v1.y = __expf(v1.y - mx);
    v1.z = __expf(v1.z - mx); v1.w = __expf(v1.w - mx);

    float s = v0.x + v0.y + v0.z + v0.w + v1.x + v1.y + v1.z + v1.w;
    #pragma unroll
    for (int o = 16; o > 0; o >>= 1) s += __shfl_xor_sync(0xffffffffu, s, o);
    if ((tid & 31) == 0) red[tid >> 5] = s;
    __syncthreads();
    s = 0.0f;
    #pragma unroll
    for (int i = 0; i < 8; i++) s += red[i];

    const float inv = 1.0f / s;
    v0.x *= inv; v0.y *= inv; v0.z *= inv; v0.w *= inv;
    v1.x *= inv; v1.y *= inv; v1.z *= inv; v1.w *= inv;
    row[tid] = v0;
    row[tid + 256] = v1;
}

// Y[m, :] += bias (N = D_), vectorized float4
__global__ void bias_add_kernel(float* __restrict__ Y, const float* __restrict__ bias,
                                long long total4)
{
    long long i = (long long)blockIdx.x * blockDim.x + threadIdx.x;
    if (i >= total4) return;
    float4 v = reinterpret_cast<float4*>(Y)[i];
    int n4 = (int)(i % (D_ / 4)) * 4;
    v.x += bias[n4 + 0];
    v.y += bias[n4 + 1];
    v.z += bias[n4 + 2];
    v.w += bias[n4 + 3];
    reinterpret_cast<float4*>(Y)[i] = v;
}

extern "C" void kernel_launch(void* const* d_in, const int* in_sizes, int n_in,
                              void* d_out, int out_size)
{
    const float* x  = (const float*)d_in[0];
    const float* Wq = (const float*)d_in[1];
    const float* bq = (const float*)d_in[2];
    const float* Wk = (const float*)d_in[3];
    const float* bk = (const float*)d_in[4];
    const float* Wv = (const float*)d_in[5];
    const float* bv = (const float*)d_in[6];
    const float* Wp = (const float*)d_in[7];
    const float* bp = (const float*)d_in[8];
    float* out = (float*)d_out;

    float *pQ, *pK, *pV, *pP, *pO;
    cudaGetSymbolAddress((void**)&pQ, g_Q);
    cudaGetSymbolAddress((void**)&pK, g_K);
    cudaGetSymbolAddress((void**)&pV, g_V);
    cudaGetSymbolAddress((void**)&pP, g_P);
    cudaGetSymbolAddress((void**)&pO, g_O);

    const float inv_scale = 1.0f / sqrtf((float)D_);
    const long long sSD = (long long)S_ * D_;
    const long long sSS = (long long)S_ * S_;
    const long long qkv4 = (long long)B_ * S_ * (D_ / 4);

    dim3 blk(256);
    dim3 gQKV(D_ / BN, (B_ * S_) / BM, 1);  // (6, 128)
    dim3 gS(S_ / BN, S_ / BM, B_);          // (16, 16, 8)
    dim3 gPV(D_ / BN, S_ / BM, B_);         // (6, 16, 8)
    dim3 gBias((unsigned)((qkv4 + 255) / 256));

    // Q = x @ Wq^T ; K = x @ Wk^T ; V = x @ Wv^T
    gemm_kernel<0><<<gQKV, blk>>>(x, Wq, pQ, D_, D_, D_, D_, 1.0f, 0, 0, 0);
    gemm_kernel<0><<<gQKV, blk>>>(x, Wk, pK, D_, D_, D_, D_, 1.0f, 0, 0, 0);
    gemm_kernel<0><<<gQKV, blk>>>(x, Wv, pV, D_, D_, D_, D_, 1.0f, 0, 0, 0);
    bias_add_kernel<<<gBias, blk>>>(pQ, bq, qkv4);
    bias_add_kernel<<<gBias, blk>>>(pK, bk, qkv4);
    bias_add_kernel<<<gBias, blk>>>(pV, bv, qkv4);

    // scores = (Q @ K^T) / sqrt(D), per batch
    gemm_kernel<0><<<gS, blk>>>(pQ, pK, pP, D_, D_, D_, S_, inv_scale, sSD, sSD, sSS);

    // softmax over last dim
    softmax_kernel<<<B_ * S_, blk>>>(pP);

    // O = P @ V, per batch (NN layout)
    gemm_kernel<1><<<gPV, blk>>>(pP, pV, pO, S_, S_, D_, D_, 1.0f, sSS, sSD, sSD);

    // out = O @ Wp^T + bp
    gemm_kernel<0><<<gQKV, blk>>>(pO, Wp, out, D_, D_, D_, D_, 1.0f, 0, 0, 0);
    bias_add_kernel<<<gBias, blk>>>(out, bp, qkv4);
}

// round 13
// speedup vs baseline: 1.1734x; 1.1734x over previous
#include <cuda_runtime.h>
#include <mma.h>
#include <math.h>

using namespace nvcuda;

#define B_ 8
#define S_ 2048
#define D_ 768

constexpr int BM = 128, BN = 256, BK = 16, KP = BK + 4;
constexpr int BNP = BN + 4;                 // stride for [k][n] B-tile layout (NN path)
constexpr int STAGE_F = BM * KP + BN * KP;  // floats per stage (A tile + B tile region)
constexpr int DSMEM = 2 * STAGE_F * (int)sizeof(float);  // 61440 bytes

// Scratch (allocation-free contract: __device__ globals)
__device__ float g_Q[(size_t)B_ * S_ * D_];
__device__ float g_K[(size_t)B_ * S_ * D_];
__device__ float g_V[(size_t)B_ * S_ * D_];
__device__ float g_P[(size_t)B_ * S_ * S_];
__device__ float g_O[(size_t)B_ * S_ * D_];

// ---- cp.async helpers (16B) ----
__device__ __forceinline__ void cp_async16(void* smem_dst, const void* gmem_src) {
    unsigned dst = (unsigned)__cvta_generic_to_shared(smem_dst);
    asm volatile("cp.async.cg.shared.global [%0], [%1], 16;\n" :: "r"(dst), "l"(gmem_src));
}
__device__ __forceinline__ void cp_async_commit() {
    asm volatile("cp.async.commit_group;\n");
}
template <int N>
__device__ __forceinline__ void cp_async_wait() {
    asm volatile("cp.async.wait_group %0;\n" :: "n"(N));
}

// C[m,n] = alpha * sum_k A[m,k] * Bx[n,k]
// BLAYOUT 0: Bm is [N,K] row-major (ldb = K stride) -> "NT" gemm. Smem Bs = [n][k].
// BLAYOUT 1: Bm is [K,N] row-major (ldb = N stride) -> "NN" gemm. Smem Bs = [k][n].
// CTA tile 128x256, 8 warps (2x4), warp tile 64x64, TF32 wmma m16n16k8, fp32 accum.
template <int BLAYOUT>
__global__ __launch_bounds__(256, 1) void gemm_kernel(
    const float* __restrict__ A, const float* __restrict__ Bm, float* __restrict__ C,
    int K, int lda, int ldb, int ldc, float alpha,
    long long strideA, long long strideB, long long strideC)
{
    extern __shared__ float sm[];

    const int tid = threadIdx.x;
    const int m0 = blockIdx.y * BM;
    const int n0 = blockIdx.x * BN;
    A  += (long long)blockIdx.z * strideA;
    Bm += (long long)blockIdx.z * strideB;
    C  += (long long)blockIdx.z * strideC;

    const int warpId = tid >> 5;
    const int wm0 = (warpId >> 2) * 64;   // 2 warp rows
    const int wn0 = (warpId & 3) * 64;    // 4 warp cols

    // ---- tile load (stage buffer b) ----
    auto issue_tile = [&](int k0, int b) {
        float* As = sm + b * STAGE_F;
        float* Bs = As + BM * KP;
        // A tile: BM x BK = 512 float4, 2 per thread
        #pragma unroll
        for (int r = 0; r < 2; r++) {
            int f = tid + r * 256;
            int row = f >> 2, kq = f & 3;
            cp_async16(&As[row * KP + kq * 4],
                       &A[(size_t)(m0 + row) * lda + k0 + kq * 4]);
        }
        if (BLAYOUT == 0) {
            // B tile: BN x BK = 1024 float4, 4 per thread
            #pragma unroll
            for (int r = 0; r < 4; r++) {
                int f = tid + r * 256;
                int row = f >> 2, kq = f & 3;
                cp_async16(&Bs[row * KP + kq * 4],
                           &Bm[(size_t)(n0 + row) * ldb + k0 + kq * 4]);
            }
        } else {
            // B tile: BK x BN = 1024 float4, 4 per thread
            #pragma unroll
            for (int r = 0; r < 4; r++) {
                int f = tid + r * 256;
                int k = f >> 6, nq = f & 63;
                cp_async16(&Bs[k * BNP + nq * 4],
                           &Bm[(size_t)(k0 + k) * ldb + n0 + nq * 4]);
            }
        }
        cp_async_commit();
    };

    wmma::fragment<wmma::accumulator, 16, 16, 8, float> acc[4][4];
    #pragma unroll
    for (int i = 0; i < 4; i++)
        #pragma unroll
        for (int j = 0; j < 4; j++)
            wmma::fill_fragment(acc[i][j], 0.0f);

    const int nIter = K / BK;
    issue_tile(0, 0);

    for (int it = 0; it < nIter; it++) {
        if (it + 1 < nIter) {
            issue_tile((it + 1) * BK, (it + 1) & 1);
            cp_async_wait<1>();
        } else {
            cp_async_wait<0>();
        }
        __syncthreads();

        const float* As = sm + (it & 1) * STAGE_F;
        const float* Bs = As + BM * KP;
        #pragma unroll
        for (int kk = 0; kk < BK; kk += 8) {
            wmma::fragment<wmma::matrix_a, 16, 16, 8, wmma::precision::tf32, wmma::row_major> af[4];
            #pragma unroll
            for (int i = 0; i < 4; i++) {
                wmma::load_matrix_sync(af[i], &As[(wm0 + i * 16) * KP + kk], KP);
                #pragma unroll
                for (int t = 0; t < af[i].num_elements; t++)
                    af[i].x[t] = wmma::__float_to_tf32(af[i].x[t]);
            }
            if (BLAYOUT == 0) {
                wmma::fragment<wmma::matrix_b, 16, 16, 8, wmma::precision::tf32, wmma::col_major> bf[4];
                #pragma unroll
                for (int j = 0; j < 4; j++) {
                    wmma::load_matrix_sync(bf[j], &Bs[(wn0 + j * 16) * KP + kk], KP);
                    #pragma unroll
                    for (int t = 0; t < bf[j].num_elements; t++)
                        bf[j].x[t] = wmma::__float_to_tf32(bf[j].x[t]);
                }
                #pragma unroll
                for (int i = 0; i < 4; i++)
                    #pragma unroll
                    for (int j = 0; j < 4; j++)
                        wmma::mma_sync(acc[i][j], af[i], bf[j], acc[i][j]);
            } else {
                wmma::fragment<wmma::matrix_b, 16, 16, 8, wmma::precision::tf32, wmma::row_major> bf[4];
                #pragma unroll
                for (int j = 0; j < 4; j++) {
                    wmma::load_matrix_sync(bf[j], &Bs[kk * BNP + wn0 + j * 16], BNP);
                    #pragma unroll
                    for (int t = 0; t < bf[j].num_elements; t++)
                        bf[j].x[t] = wmma::__float_to_tf32(bf[j].x[t]);
                }
                #pragma unroll
                for (int i = 0; i < 4; i++)
                    #pragma unroll
                    for (int j = 0; j < 4; j++)
                        wmma::mma_sync(acc[i][j], af[i], bf[j], acc[i][j]);
            }
        }
        __syncthreads();  // all warps done with this buffer before it is refilled
    }

    #pragma unroll
    for (int i = 0; i < 4; i++)
        #pragma unroll
        for (int j = 0; j < 4; j++) {
            #pragma unroll
            for (int t = 0; t < acc[i][j].num_elements; t++)
                acc[i][j].x[t] *= alpha;
            wmma::store_matrix_sync(
                &C[(size_t)(m0 + wm0 + i * 16) * ldc + n0 + wn0 + j * 16],
                acc[i][j], ldc, wmma::mem_row_major);
        }
}

// Row softmax over g_P rows of length S_ (one block per row, 256 threads, 8 elems each)
__global__ __launch_bounds__(256) void softmax_kernel(float* __restrict__ P)
{
    float4* row = reinterpret_cast<float4*>(P + (size_t)blockIdx.x * S_);
    const int tid = threadIdx.x;
    float4 v0 = row[tid];
    float4 v1 = row[tid + 256];

    float mx = fmaxf(fmaxf(fmaxf(v0.x, v0.y), fmaxf(v0.z, v0.w)),
                     fmaxf(fmaxf(v1.x, v1.y), fmaxf(v1.z, v1.w)));
    __shared__ float red[8];
    #pragma unroll
    for (int o = 16; o > 0; o >>= 1) mx = fmaxf(mx, __shfl_xor_sync(0xffffffffu, mx, o));
    if ((tid & 31) == 0) red[tid >> 5] = mx;
    __syncthreads();
    mx = red[0];
    #pragma unroll
    for (int i = 1; i < 8; i++) mx = fmaxf(mx, red[i]);
    __syncthreads();

    v0.x = __expf(v0.x - mx); v0.y = __expf(v0.y - mx);
    v0.z = __expf(v0.z - mx); v0.w = __expf(v0.w - mx);
    v1.x = __expf(v1.x - mx); v1.y = __expf(v1.y - mx);
    v1.z = __expf(v1.z - mx); v1.w = __expf(v1.w - mx);

    float s = v0.x + v0.y + v0.z + v0.w + v1.x + v1.y + v1.z + v1.w;
    #pragma unroll
    for (int o = 16; o > 0; o >>= 1) s += __shfl_xor_sync(0xffffffffu, s, o);
    if ((tid & 31) == 0) red[tid >> 5] = s;
    __syncthreads();
    s = 0.0f;
    #pragma unroll
    for (int i = 0; i < 8; i++) s += red[i];

    const float inv = 1.0f / s;
    v0.x *= inv; v0.y *= inv; v0.z *= inv; v0.w *= inv;
    v1.x *= inv; v1.y *= inv; v1.z *= inv; v1.w *= inv;
    row[tid] = v0;
    row[tid + 256] = v1;
}

// Y[m, :] += bias (N = D_), vectorized float4
__global__ void bias_add_kernel(float* __restrict__ Y, const float* __restrict__ bias,
                                long long total4)
{
    long long i = (long long)blockIdx.x * blockDim.x + threadIdx.x;
    if (i >= total4) return;
    float4 v = reinterpret_cast<float4*>(Y)[i];
    int n4 = (int)(i % (D_ / 4)) * 4;
    v.x += bias[n4 + 0];
    v.y += bias[n4 + 1];
    v.z += bias[n4 + 2];
    v.w += bias[n4 + 3];
    reinterpret_cast<float4*>(Y)[i] = v;
}

extern "C" void kernel_launch(void* const* d_in, const int* in_sizes, int n_in,
                              void* d_out, int out_size)
{
    const float* x  = (const float*)d_in[0];
    const float* Wq = (const float*)d_in[1];
    const float* bq = (const float*)d_in[2];
    const float* Wk = (const float*)d_in[3];
    const float* bk = (const float*)d_in[4];
    const float* Wv = (const float*)d_in[5];
    const float* bv = (const float*)d_in[6];
    const float* Wp = (const float*)d_in[7];
    const float* bp = (const float*)d_in[8];
    float* out = (float*)d_out;

    float *pQ, *pK, *pV, *pP, *pO;
    cudaGetSymbolAddress((void**)&pQ, g_Q);
    cudaGetSymbolAddress((void**)&pK, g_K);
    cudaGetSymbolAddress((void**)&pV, g_V);
    cudaGetSymbolAddress((void**)&pP, g_P);
    cudaGetSymbolAddress((void**)&pO, g_O);

    cudaFuncSetAttribute(gemm_kernel<0>, cudaFuncAttributeMaxDynamicSharedMemorySize, DSMEM);
    cudaFuncSetAttribute(gemm_kernel<1>, cudaFuncAttributeMaxDynamicSharedMemorySize, DSMEM);

    const float inv_scale = 1.0f / sqrtf((float)D_);
    const long long sSD = (long long)S_ * D_;
    const long long sSS = (long long)S_ * S_;
    const long long qkv4 = (long long)B_ * S_ * (D_ / 4);

    dim3 blk(256);
    dim3 gQKV(D_ / BN, (B_ * S_) / BM, 1);  // (3, 128)
    dim3 gS(S_ / BN, S_ / BM, B_);          // (8, 16, 8)
    dim3 gPV(D_ / BN, S_ / BM, B_);         // (3, 16, 8)
    dim3 gBias((unsigned)((qkv4 + 255) / 256));

    // Launch order arranged so launch #6 (ncu -s 5 -c 1) is the scores GEMM.
    // 1-3) Q = x@Wq^T ; K = x@Wk^T ; V = x@Wv^T
    gemm_kernel<0><<<gQKV, blk, DSMEM>>>(x, Wq, pQ, D_, D_, D_, D_, 1.0f, 0, 0, 0);
    gemm_kernel<0><<<gQKV, blk, DSMEM>>>(x, Wk, pK, D_, D_, D_, D_, 1.0f, 0, 0, 0);
    gemm_kernel<0><<<gQKV, blk, DSMEM>>>(x, Wv, pV, D_, D_, D_, D_, 1.0f, 0, 0, 0);
    // 4-5) biases needed by scores
    bias_add_kernel<<<gBias, blk>>>(pQ, bq, qkv4);
    bias_add_kernel<<<gBias, blk>>>(pK, bk, qkv4);
    // 6) scores = (Q @ K^T) / sqrt(D), per batch   <-- profiled launch
    gemm_kernel<0><<<gS, blk, DSMEM>>>(pQ, pK, pP, D_, D_, D_, S_, inv_scale, sSD, sSD, sSS);
    // 7) V bias (only needed before PV)
    bias_add_kernel<<<gBias, blk>>>(pV, bv, qkv4);
    // 8) softmax over last dim
    softmax_kernel<<<B_ * S_, blk>>>(pP);
    // 9) O = P @ V, per batch (NN layout)
    gemm_kernel<1><<<gPV, blk, DSMEM>>>(pP, pV, pO, S_, S_, D_, D_, 1.0f, sSS, sSD, sSD);
    // 10) out = O @ Wp^T + bp
    gemm_kernel<0><<<gQKV, blk, DSMEM>>>(pO, Wp, out, D_, D_, D_, D_, 1.0f, 0, 0, 0);
    bias_add_kernel<<<gBias, blk>>>(out, bp, qkv4);
}

// round 15
// speedup vs baseline: 1.2391x; 1.0560x over previous
#include <cuda_runtime.h>
#include <mma.h>
#include <math.h>

using namespace nvcuda;

#define B_ 8
#define S_ 2048
#define D_ 768

constexpr int BM = 128, BN = 256, BK = 32, KP = BK + 4;
constexpr int BNP = BN + 4;                 // stride for [k][n] B-tile layout (NN path)
constexpr int STAGE_F = BM * KP + BN * KP;  // floats per stage
constexpr int DSMEM = 2 * STAGE_F * (int)sizeof(float);  // 110592 bytes

// Scratch (allocation-free contract: __device__ globals)
__device__ float g_Q[(size_t)B_ * S_ * D_];
__device__ float g_K[(size_t)B_ * S_ * D_];
__device__ float g_V[(size_t)B_ * S_ * D_];
__device__ float g_P[(size_t)B_ * S_ * S_];
__device__ float g_O[(size_t)B_ * S_ * D_];

// ---- cp.async helpers (16B) ----
__device__ __forceinline__ void cp_async16(void* smem_dst, const void* gmem_src) {
    unsigned dst = (unsigned)__cvta_generic_to_shared(smem_dst);
    asm volatile("cp.async.cg.shared.global [%0], [%1], 16;\n" :: "r"(dst), "l"(gmem_src));
}
__device__ __forceinline__ void cp_async_commit() {
    asm volatile("cp.async.commit_group;\n");
}
template <int N>
__device__ __forceinline__ void cp_async_wait() {
    asm volatile("cp.async.wait_group %0;\n" :: "n"(N));
}

// C[m,n] = alpha * sum_k A[m,k] * Bx[n,k]
// BLAYOUT 0: Bm is [N,K] row-major (ldb = K stride) -> "NT" gemm. Smem Bs = [n][k].
// BLAYOUT 1: Bm is [K,N] row-major (ldb = N stride) -> "NN" gemm. Smem Bs = [k][n].
// CTA tile 128x256, 8 warps (2x4), warp tile 64x64, TF32 wmma m16n16k8, fp32 accum.
template <int BLAYOUT>
__global__ __launch_bounds__(256, 1) void gemm_kernel(
    const float* __restrict__ A, const float* __restrict__ Bm, float* __restrict__ C,
    int K, int lda, int ldb, int ldc, float alpha,
    long long strideA, long long strideB, long long strideC)
{
    extern __shared__ float sm[];

    const int tid = threadIdx.x;
    const int m0 = blockIdx.y * BM;
    const int n0 = blockIdx.x * BN;
    A  += (long long)blockIdx.z * strideA;
    Bm += (long long)blockIdx.z * strideB;
    C  += (long long)blockIdx.z * strideC;

    const int warpId = tid >> 5;
    const int wm0 = (warpId >> 2) * 64;   // 2 warp rows
    const int wn0 = (warpId & 3) * 64;    // 4 warp cols

    // ---- tile load (stage buffer b) ----
    auto issue_tile = [&](int k0, int b) {
        float* As = sm + b * STAGE_F;
        float* Bs = As + BM * KP;
        // A tile: BM x BK = 1024 float4, 4 per thread
        #pragma unroll
        for (int r = 0; r < 4; r++) {
            int f = tid + r * 256;
            int row = f >> 3, kq = f & 7;
            cp_async16(&As[row * KP + kq * 4],
                       &A[(size_t)(m0 + row) * lda + k0 + kq * 4]);
        }
        if (BLAYOUT == 0) {
            // B tile: BN x BK = 2048 float4, 8 per thread
            #pragma unroll
            for (int r = 0; r < 8; r++) {
                int f = tid + r * 256;
                int row = f >> 3, kq = f & 7;
                cp_async16(&Bs[row * KP + kq * 4],
                           &Bm[(size_t)(n0 + row) * ldb + k0 + kq * 4]);
            }
        } else {
            // B tile: BK x BN = 2048 float4, 8 per thread
            #pragma unroll
            for (int r = 0; r < 8; r++) {
                int f = tid + r * 256;
                int k = f >> 6, nq = f & 63;
                cp_async16(&Bs[k * BNP + nq * 4],
                           &Bm[(size_t)(k0 + k) * ldb + n0 + nq * 4]);
            }
        }
        cp_async_commit();
    };

    wmma::fragment<wmma::accumulator, 16, 16, 8, float> acc[4][4];
    #pragma unroll
    for (int i = 0; i < 4; i++)
        #pragma unroll
        for (int j = 0; j < 4; j++)
            wmma::fill_fragment(acc[i][j], 0.0f);

    const int nIter = K / BK;
    issue_tile(0, 0);

    for (int it = 0; it < nIter; it++) {
        if (it + 1 < nIter) {
            issue_tile((it + 1) * BK, (it + 1) & 1);
            cp_async_wait<1>();
        } else {
            cp_async_wait<0>();
        }
        __syncthreads();

        const float* As = sm + (it & 1) * STAGE_F;
        const float* Bs = As + BM * KP;
        #pragma unroll
        for (int kk = 0; kk < BK; kk += 8) {
            wmma::fragment<wmma::matrix_a, 16, 16, 8, wmma::precision::tf32, wmma::row_major> af[4];
            #pragma unroll
            for (int i = 0; i < 4; i++) {
                wmma::load_matrix_sync(af[i], &As[(wm0 + i * 16) * KP + kk], KP);
                #pragma unroll
                for (int t = 0; t < af[i].num_elements; t++)
                    af[i].x[t] = wmma::__float_to_tf32(af[i].x[t]);
            }
            if (BLAYOUT == 0) {
                wmma::fragment<wmma::matrix_b, 16, 16, 8, wmma::precision::tf32, wmma::col_major> bf[4];
                #pragma unroll
                for (int j = 0; j < 4; j++) {
                    wmma::load_matrix_sync(bf[j], &Bs[(wn0 + j * 16) * KP + kk], KP);
                    #pragma unroll
                    for (int t = 0; t < bf[j].num_elements; t++)
                        bf[j].x[t] = wmma::__float_to_tf32(bf[j].x[t]);
                }
                #pragma unroll
                for (int i = 0; i < 4; i++)
                    #pragma unroll
                    for (int j = 0; j < 4; j++)
                        wmma::mma_sync(acc[i][j], af[i], bf[j], acc[i][j]);
            } else {
                wmma::fragment<wmma::matrix_b, 16, 16, 8, wmma::precision::tf32, wmma::row_major> bf[4];
                #pragma unroll
                for (int j = 0; j < 4; j++) {
                    wmma::load_matrix_sync(bf[j], &Bs[kk * BNP + wn0 + j * 16], BNP);
                    #pragma unroll
                    for (int t = 0; t < bf[j].num_elements; t++)
                        bf[j].x[t] = wmma::__float_to_tf32(bf[j].x[t]);
                }
                #pragma unroll
                for (int i = 0; i < 4; i++)
                    #pragma unroll
                    for (int j = 0; j < 4; j++)
                        wmma::mma_sync(acc[i][j], af[i], bf[j], acc[i][j]);
            }
        }
        __syncthreads();  // all warps done with this buffer before it is refilled
    }

    #pragma unroll
    for (int i = 0; i < 4; i++)
        #pragma unroll
        for (int j = 0; j < 4; j++) {
            #pragma unroll
            for (int t = 0; t < acc[i][j].num_elements; t++)
                acc[i][j].x[t] *= alpha;
            wmma::store_matrix_sync(
                &C[(size_t)(m0 + wm0 + i * 16) * ldc + n0 + wn0 + j * 16],
                acc[i][j], ldc, wmma::mem_row_major);
        }
}

// Row softmax over g_P rows of length S_ (one block per row, 256 threads, 8 elems each)
__global__ __launch_bounds__(256) void softmax_kernel(float* __restrict__ P)
{
    float4* row = reinterpret_cast<float4*>(P + (size_t)blockIdx.x * S_);
    const int tid = threadIdx.x;
    float4 v0 = row[tid];
    float4 v1 = row[tid + 256];

    float mx = fmaxf(fmaxf(fmaxf(v0.x, v0.y), fmaxf(v0.z, v0.w)),
                     fmaxf(fmaxf(v1.x, v1.y), fmaxf(v1.z, v1.w)));
    __shared__ float red[8];
    #pragma unroll
    for (int o = 16; o > 0; o >>= 1) mx = fmaxf(mx, __shfl_xor_sync(0xffffffffu, mx, o));
    if ((tid & 31) == 0) red[tid >> 5] = mx;
    __syncthreads();
    mx = red[0];
    #pragma unroll
    for (int i = 1; i < 8; i++) mx = fmaxf(mx, red[i]);
    __syncthreads();

    v0.x = __expf(v0.x - mx); v0.y = __expf(v0.y - mx);
    v0.z = __expf(v0.z - mx); v0.w = __expf(v0.w - mx);
    v1.x = __expf(v1.x - mx); v1.y = __expf(v1.y - mx);
    v1.z = __expf(v1.z - mx); v1.w = __expf(v1.w - mx);

    float s = v0.x + v0.y + v0.z + v0.w + v1.x + v1.y + v1.z + v1.w;
    #pragma unroll
    for (int o = 16; o > 0; o >>= 1) s += __shfl_xor_sync(0xffffffffu, s, o);
    if ((tid & 31) == 0) red[tid >> 5] = s;
    __syncthreads();
    s = 0.0f;
    #pragma unroll
    for (int i = 0; i < 8; i++) s += red[i];

    const float inv = 1.0f / s;
    v0.x *= inv; v0.y *= inv; v0.z *= inv; v0.w *= inv;
    v1.x *= inv; v1.y *= inv; v1.z *= inv; v1.w *= inv;
    row[tid] = v0;
    row[tid + 256] = v1;
}

// Y[m, :] += bias (N = D_), vectorized float4
__global__ void bias_add_kernel(float* __restrict__ Y, const float* __restrict__ bias,
                                long long total4)
{
    long long i = (long long)blockIdx.x * blockDim.x + threadIdx.x;
    if (i >= total4) return;
    float4 v = reinterpret_cast<float4*>(Y)[i];
    int n4 = (int)(i % (D_ / 4)) * 4;
    v.x += bias[n4 + 0];
    v.y += bias[n4 + 1];
    v.z += bias[n4 + 2];
    v.w += bias[n4 + 3];
    reinterpret_cast<float4*>(Y)[i] = v;
}

extern "C" void kernel_launch(void* const* d_in, const int* in_sizes, int n_in,
                              void* d_out, int out_size)
{
    const float* x  = (const float*)d_in[0];
    const float* Wq = (const float*)d_in[1];
    const float* bq = (const float*)d_in[2];
    const float* Wk = (const float*)d_in[3];
    const float* bk = (const float*)d_in[4];
    const float* Wv = (const float*)d_in[5];
    const float* bv = (const float*)d_in[6];
    const float* Wp = (const float*)d_in[7];
    const float* bp = (const float*)d_in[8];
    float* out = (float*)d_out;

    float *pQ, *pK, *pV, *pP, *pO;
    cudaGetSymbolAddress((void**)&pQ, g_Q);
    cudaGetSymbolAddress((void**)&pK, g_K);
    cudaGetSymbolAddress((void**)&pV, g_V);
    cudaGetSymbolAddress((void**)&pP, g_P);
    cudaGetSymbolAddress((void**)&pO, g_O);

    cudaFuncSetAttribute(gemm_kernel<0>, cudaFuncAttributeMaxDynamicSharedMemorySize, DSMEM);
    cudaFuncSetAttribute(gemm_kernel<1>, cudaFuncAttributeMaxDynamicSharedMemorySize, DSMEM);

    const float inv_scale = 1.0f / sqrtf((float)D_);
    const long long sSD = (long long)S_ * D_;
    const long long sSS = (long long)S_ * S_;
    const long long qkv4 = (long long)B_ * S_ * (D_ / 4);

    dim3 blk(256);
    dim3 gQKV(D_ / BN, (B_ * S_) / BM, 1);  // (3, 128)
    dim3 gS(S_ / BN, S_ / BM, B_);          // (8, 16, 8)
    dim3 gPV(D_ / BN, S_ / BM, B_);         // (3, 16, 8)
    dim3 gBias((unsigned)((qkv4 + 255) / 256));

    // The harness issues ONE launch before ours (observed: -s 5 -c 1 captured
    // our launch #5). Place the scores GEMM at our #5 so it gets profiled.
    // 1-2) Q = x@Wq^T ; K = x@Wk^T
    gemm_kernel<0><<<gQKV, blk, DSMEM>>>(x, Wq, pQ, D_, D_, D_, D_, 1.0f, 0, 0, 0);
    gemm_kernel<0><<<gQKV, blk, DSMEM>>>(x, Wk, pK, D_, D_, D_, D_, 1.0f, 0, 0, 0);
    // 3-4) biases needed by scores
    bias_add_kernel<<<gBias, blk>>>(pQ, bq, qkv4);
    bias_add_kernel<<<gBias, blk>>>(pK, bk, qkv4);
    // 5) scores = (Q @ K^T) / sqrt(D), per batch   <-- profiled launch
    gemm_kernel<0><<<gS, blk, DSMEM>>>(pQ, pK, pP, D_, D_, D_, S_, inv_scale, sSD, sSD, sSS);
    // 6-7) V = x@Wv^T (+bias) — only needed before PV
    gemm_kernel<0><<<gQKV, blk, DSMEM>>>(x, Wv, pV, D_, D_, D_, D_, 1.0f, 0, 0, 0);
    bias_add_kernel<<<gBias, blk>>>(pV, bv, qkv4);
    // 8) softmax over last dim
    softmax_kernel<<<B_ * S_, blk>>>(pP);
    // 9) O = P @ V, per batch (NN layout)
    gemm_kernel<1><<<gPV, blk, DSMEM>>>(pP, pV, pO, S_, S_, D_, D_, 1.0f, sSS, sSD, sSD);
    // 10) out = O @ Wp^T + bp
    gemm_kernel<0><<<gQKV, blk, DSMEM>>>(pO, Wp, out, D_, D_, D_, D_, 1.0f, 0, 0, 0);
    bias_add_kernel<<<gBias, blk>>>(out, bp, qkv4);
}